// round 3
// baseline (speedup 1.0000x reference)
#include <cuda_runtime.h>
#include <math_constants.h>

// Problem constants
#define Bb 2
#define Hh 16
#define Ss 2048
#define Dd 64

// Tiling
#define TQ 128
#define TK 64
#define NT 256
#define KTILES (Ss / TK)        // 32
#define QS_STRIDE 132           // 128 + 4 pad (keeps float4 alignment)
#define KS_STRIDE 68            // 64 + 4 pad
// smem: sweep1 = q_s[64*132] + k_s[64*68] = 12800 floats
//       sweep2 = v_s[64*68]  + p_s[128*68] = 13056 floats
#define SMEM_FLOATS 13056

// 1 -> mask elements are 4 bytes (int32 or float32; masked iff word != 0)
// 0 -> mask elements are 1 byte  (packed bools)
__device__ int g_mask_elem4;

__global__ void detect_mask_kernel(const unsigned int* __restrict__ mw)
{
    // Scan the first 4096 32-bit words of the mask buffer.
    int has_bigbyte = 0;   // any byte value > 1  -> float32 elements
    int has_bigword = 0;   // any word value > 1  -> packed uint8 (if no big byte)
    for (int i = threadIdx.x; i < 4096; i += NT) {
        unsigned w = mw[i];
        unsigned b0 = w & 0xffu, b1 = (w >> 8) & 0xffu,
                 b2 = (w >> 16) & 0xffu, b3 = (w >> 24) & 0xffu;
        if (b0 > 1u || b1 > 1u || b2 > 1u || b3 > 1u) has_bigbyte = 1;
        if (w > 1u) has_bigword = 1;
    }
    has_bigbyte = __syncthreads_or(has_bigbyte);
    has_bigword = __syncthreads_or(has_bigword);
    if (threadIdx.x == 0) {
        // bytes>1 -> float32 (4B). words>1 but bytes<=1 -> uint8 (1B).
        // all words in {0,1} -> int32 (4B).
        g_mask_elem4 = has_bigbyte ? 1 : (has_bigword ? 0 : 1);
    }
}

__global__ __launch_bounds__(NT, 2)
void attn_fused_kernel(const float* __restrict__ Qg_,
                       const float* __restrict__ Kg_,
                       const float* __restrict__ Vg_,
                       const void* __restrict__ Mg_,
                       float* __restrict__ ctx_out,
                       float* __restrict__ att_out)
{
    extern __shared__ float sm[];
    float* q_s = sm;                     // [64][QS_STRIDE]  d-major Q tile (sweep 1)
    float* k_s = sm + 64 * QS_STRIDE;    // [64][KS_STRIDE]  d-major K tile (sweep 1)
    float* v_s = sm;                     // [64][KS_STRIDE]  k-major V tile (sweep 2)
    float* p_s = sm + 64 * KS_STRIDE;    // [128][KS_STRIDE] probs tile     (sweep 2)

    const int tid = threadIdx.x;
    const int tx = tid & 15;             // k / d direction (16)
    const int ty = tid >> 4;             // q direction (16)
    const int qt = blockIdx.x;           // q tile index
    const int bh = blockIdx.y;           // fused (b, h)
    const int b  = bh >> 4;
    const int q0 = qt * TQ;

    const bool mask4 = (g_mask_elem4 != 0);

    const size_t head_off = (size_t)bh * Ss * Dd;
    const float* Qg = Qg_ + head_off + (size_t)q0 * Dd;
    const float* Kg = Kg_ + head_off;
    const float* Vg = Vg_ + head_off;
    const size_t mask_row0 = (size_t)b * Ss * Ss + (size_t)q0 * Ss;
    const unsigned char* Mg1 = (const unsigned char*)Mg_ + mask_row0;
    const unsigned int*  Mg4 = (const unsigned int*)Mg_ + mask_row0;
    float* att = att_out + (size_t)bh * Ss * Ss + (size_t)q0 * Ss;
    float* ctx = ctx_out + head_off + (size_t)q0 * Dd;

    // ---- Load Q tile (transposed to d-major) ----
    for (int idx = tid; idx < TQ * Dd; idx += NT) {
        int q = idx >> 6;
        int d = idx & 63;
        q_s[d * QS_STRIDE + q] = Qg[idx];
    }

    float m[8], l[8];
#pragma unroll
    for (int i = 0; i < 8; i++) { m[i] = -CUDART_INF_F; l[i] = 0.0f; }

    const float scale = 0.125f;          // 1/sqrt(64)
    const float NEG = -1e9f;

    // ================= Sweep 1: scores + online (m, l) =================
    for (int kt = 0; kt < KTILES; kt++) {
        // Load K tile (transposed to d-major)
        for (int idx = tid; idx < TK * Dd; idx += NT) {
            int k = idx >> 6;
            int d = idx & 63;
            k_s[d * KS_STRIDE + k] = Kg[(size_t)kt * TK * Dd + idx];
        }
        __syncthreads();

        float acc[8][4];
#pragma unroll
        for (int i = 0; i < 8; i++)
#pragma unroll
            for (int j = 0; j < 4; j++) acc[i][j] = 0.0f;

#pragma unroll 8
        for (int d = 0; d < Dd; d++) {
            float4 kf = *(const float4*)&k_s[d * KS_STRIDE + tx * 4];
            float4 qa = *(const float4*)&q_s[d * QS_STRIDE + ty * 8];
            float4 qb = *(const float4*)&q_s[d * QS_STRIDE + ty * 8 + 4];
            float qf[8] = {qa.x, qa.y, qa.z, qa.w, qb.x, qb.y, qb.z, qb.w};
#pragma unroll
            for (int i = 0; i < 8; i++) {
                acc[i][0] = fmaf(qf[i], kf.x, acc[i][0]);
                acc[i][1] = fmaf(qf[i], kf.y, acc[i][1]);
                acc[i][2] = fmaf(qf[i], kf.z, acc[i][2]);
                acc[i][3] = fmaf(qf[i], kf.w, acc[i][3]);
            }
        }

        // Epilogue: scale + mask, write raw scores, online max/sum
        const int kc = kt * TK + tx * 4;
#pragma unroll
        for (int i = 0; i < 8; i++) {
            const int q = ty * 8 + i;
            bool mk0, mk1, mk2, mk3;
            if (mask4) {
                uint4 w = *(const uint4*)(Mg4 + (size_t)q * Ss + kc);
                mk0 = w.x != 0u; mk1 = w.y != 0u; mk2 = w.z != 0u; mk3 = w.w != 0u;
            } else {
                uchar4 w = *(const uchar4*)(Mg1 + (size_t)q * Ss + kc);
                mk0 = w.x != 0;  mk1 = w.y != 0;  mk2 = w.z != 0;  mk3 = w.w != 0;
            }
            float s0 = mk0 ? NEG : acc[i][0] * scale;
            float s1 = mk1 ? NEG : acc[i][1] * scale;
            float s2 = mk2 ? NEG : acc[i][2] * scale;
            float s3 = mk3 ? NEG : acc[i][3] * scale;
            *(float4*)(att + (size_t)q * Ss + kc) = make_float4(s0, s1, s2, s3);

            float mx = fmaxf(fmaxf(s0, s1), fmaxf(s2, s3));
            float nm = fmaxf(m[i], mx);
            l[i] = l[i] * __expf(m[i] - nm)
                 + __expf(s0 - nm) + __expf(s1 - nm)
                 + __expf(s2 - nm) + __expf(s3 - nm);
            m[i] = nm;
        }
        __syncthreads();
    }

    // ---- Reduce (m, l) across the 16 tx lanes (same q rows) ----
#pragma unroll
    for (int i = 0; i < 8; i++) {
        float mi = m[i], li = l[i];
#pragma unroll
        for (int off = 8; off; off >>= 1) {
            float mo = __shfl_xor_sync(0xffffffffu, mi, off);
            float lo = __shfl_xor_sync(0xffffffffu, li, off);
            float nm = fmaxf(mi, mo);
            li = li * __expf(mi - nm) + lo * __expf(mo - nm);
            mi = nm;
        }
        m[i] = mi;
        l[i] = 1.0f / li;   // keep reciprocal
    }

    // ================= Sweep 2: normalize + P·V =================
    float cacc[8][4];
#pragma unroll
    for (int i = 0; i < 8; i++)
#pragma unroll
        for (int j = 0; j < 4; j++) cacc[i][j] = 0.0f;

    for (int kt = 0; kt < KTILES; kt++) {
        __syncthreads();   // previous iter's smem reads (and sweep1 tiles) done

        // Load V tile (k-major, matches global layout)
        for (int idx = tid; idx < TK * Dd; idx += NT) {
            v_s[(idx >> 6) * KS_STRIDE + (idx & 63)] = Vg[(size_t)kt * TK * Dd + idx];
        }

        // Compute normalized probs for my 8x4 patch; write to attention + smem
        const int kc = kt * TK + tx * 4;
#pragma unroll
        for (int i = 0; i < 8; i++) {
            const int q = ty * 8 + i;
            float4 sv = *(const float4*)(att + (size_t)q * Ss + kc);
            float4 pv;
            pv.x = __expf(sv.x - m[i]) * l[i];
            pv.y = __expf(sv.y - m[i]) * l[i];
            pv.z = __expf(sv.z - m[i]) * l[i];
            pv.w = __expf(sv.w - m[i]) * l[i];
            *(float4*)(att + (size_t)q * Ss + kc) = pv;
            *(float4*)&p_s[q * KS_STRIDE + tx * 4] = pv;
        }
        __syncthreads();

        // P·V accumulate
#pragma unroll 8
        for (int k = 0; k < TK; k++) {
            float4 vf = *(const float4*)&v_s[k * KS_STRIDE + tx * 4];
#pragma unroll
            for (int i = 0; i < 8; i++) {
                float p = p_s[(ty * 8 + i) * KS_STRIDE + k];
                cacc[i][0] = fmaf(p, vf.x, cacc[i][0]);
                cacc[i][1] = fmaf(p, vf.y, cacc[i][1]);
                cacc[i][2] = fmaf(p, vf.z, cacc[i][2]);
                cacc[i][3] = fmaf(p, vf.w, cacc[i][3]);
            }
        }
    }

    // ---- Write context ----
#pragma unroll
    for (int i = 0; i < 8; i++) {
        *(float4*)(ctx + (size_t)(ty * 8 + i) * Dd + tx * 4) =
            make_float4(cacc[i][0], cacc[i][1], cacc[i][2], cacc[i][3]);
    }
}

extern "C" void kernel_launch(void* const* d_in, const int* in_sizes, int n_in,
                              void* d_out, int out_size)
{
    const float* Q = (const float*)d_in[0];
    const float* K = (const float*)d_in[1];
    const float* V = (const float*)d_in[2];
    const void*  M = d_in[3];
    // d_in[4] = dim_key (constant 64), unused

    float* out = (float*)d_out;
    float* ctx = out;                                       // [B,H,S,D]
    float* att = out + (size_t)Bb * Hh * Ss * Dd;           // [B,H,S,S]

    const size_t smem = SMEM_FLOATS * sizeof(float);        // 52224 B
    cudaFuncSetAttribute(attn_fused_kernel,
                         cudaFuncAttributeMaxDynamicSharedMemorySize, (int)smem);

    detect_mask_kernel<<<1, NT>>>((const unsigned int*)M);

    dim3 grid(Ss / TQ, Bb * Hh);                            // (16, 32) = 512 CTAs
    attn_fused_kernel<<<grid, NT, smem>>>(Q, K, V, M, ctx, att);
}